// round 3
// baseline (speedup 1.0000x reference)
#include <cuda_runtime.h>

#define Bsz   128
#define Lseq  4096
#define Hd    64
#define G3    192
#define IN2H  128
#define NCLS  230
#define BL    (Bsz * Lseq)

// Scratch (allocation-free rule: __device__ globals)
__device__ float g_gx[(size_t)2 * BL * G3];    // [dir][b][t][192]  (~805 MB)
__device__ float g_buf[(size_t)BL * IN2H];     // [b][t][128]       (~268 MB)

// ---------------- packed f32x2 / fast-math helpers ----------------
__device__ __forceinline__ unsigned long long fma2(unsigned long long a,
                                                   unsigned long long b,
                                                   unsigned long long c) {
    unsigned long long d;
    asm("fma.rn.f32x2 %0, %1, %2, %3;" : "=l"(d) : "l"(a), "l"(b), "l"(c));
    return d;
}
__device__ __forceinline__ float2 u2f2(unsigned long long v) {
    float2 f;
    asm("mov.b64 {%0, %1}, %2;" : "=f"(f.x), "=f"(f.y) : "l"(v));
    return f;
}
__device__ __forceinline__ float tanh_fast(float x) {
    float y;
    asm("tanh.approx.f32 %0, %1;" : "=f"(y) : "f"(x));
    return y;
}
__device__ __forceinline__ float sigm_fast(float x) {
    // sigmoid(x) = 0.5*tanh(0.5x) + 0.5 — single MUFU.TANH
    return fmaf(0.5f, tanh_fast(0.5f * x), 0.5f);
}

// ---------------- gx GEMM for layers 1..3 ----------------
// gx[d][row][c] = sum_k inp[row][k] * w_ih[l-1][d][c][k] + b_ih[l][d][c]
// Tile: 64 rows x 192 cols, K=128 in 4 chunks of 32 (16 f32x2 pairs).
__global__ void __launch_bounds__(256, 1)
gx_gemm_kernel(const float* __restrict__ w_ih,
               const float* __restrict__ b_ih,
               int layer) {
    const int d = blockIdx.y;
    const size_t row0 = (size_t)blockIdx.x * 64;
    const int tid = threadIdx.x;
    const int tx = tid & 15;   // col group: cols tx + 16*j, j<12
    const int ty = tid >> 4;   // row group: rows ty + 16*i, i<4

    const unsigned long long* inp2 = (const unsigned long long*)g_buf;
    const unsigned long long* w2g =
        (const unsigned long long*)(w_ih + ((size_t)(layer - 1) * 2 + d) * G3 * IN2H);

    __shared__ unsigned long long a_s[16][65];   // [kpair][row]
    __shared__ unsigned long long b_s[16][193];  // [kpair][col]

    unsigned long long acc[4][12];
#pragma unroll
    for (int i = 0; i < 4; i++)
#pragma unroll
        for (int j = 0; j < 12; j++) acc[i][j] = 0ULL;

#pragma unroll 1
    for (int ch = 0; ch < 4; ch++) {
        const int kp2 = ch * 16;  // base k-pair index (ull units)
#pragma unroll
        for (int it = 0; it < 4; it++) {
            int lin = tid + it * 256;
            int r = lin >> 4;
            int c2 = lin & 15;
            a_s[c2][r] = inp2[(row0 + r) * 64 + kp2 + c2];
        }
#pragma unroll
        for (int it = 0; it < 12; it++) {
            int lin = tid + it * 256;
            int cc = lin >> 4;
            int c2 = lin & 15;
            b_s[c2][cc] = w2g[(size_t)cc * 64 + kp2 + c2];
        }
        __syncthreads();
#pragma unroll
        for (int kp = 0; kp < 16; kp++) {
            unsigned long long a2[4], b2[12];
#pragma unroll
            for (int i = 0; i < 4; i++) a2[i] = a_s[kp][ty + 16 * i];
#pragma unroll
            for (int j = 0; j < 12; j++) b2[j] = b_s[kp][tx + 16 * j];
#pragma unroll
            for (int i = 0; i < 4; i++)
#pragma unroll
                for (int j = 0; j < 12; j++)
                    acc[i][j] = fma2(a2[i], b2[j], acc[i][j]);
        }
        __syncthreads();
    }

    const float* bih = b_ih + ((size_t)layer * 2 + d) * G3;
#pragma unroll
    for (int i = 0; i < 4; i++) {
        size_t row = row0 + ty + 16 * i;
#pragma unroll
        for (int j = 0; j < 12; j++) {
            int c = tx + 16 * j;
            float2 f = u2f2(acc[i][j]);
            g_gx[((size_t)d * BL + row) * G3 + c] = f.x + f.y + bih[c];
        }
    }
}

// ---------------- sequential GRU scan ----------------
// grid (B, 2 dirs), 192 threads (one per gate output).
// layer 0: gx computed inline from x (input size 1). layers>=1: gx streamed
// from g_gx with a depth-4 register prefetch ring to hide DRAM latency.
__global__ void __launch_bounds__(192, 2)
scan_kernel(const float* __restrict__ w_hh,
            const float* __restrict__ b_hh,
            const float* __restrict__ x,
            const float* __restrict__ w_ih0,
            const float* __restrict__ b_ih,
            int layer) {
    const int b = blockIdx.x;
    const int d = blockIdx.y;
    const int g = threadIdx.x;

    // w_hh row for this gate output, packed as f32x2
    const float* W = w_hh + (((size_t)layer * 2 + d) * G3 + g) * Hd;
    unsigned long long w2[32];
#pragma unroll
    for (int i = 0; i < 32; i++) w2[i] = ((const unsigned long long*)W)[i];
    const float bias = b_hh[((size_t)layer * 2 + d) * G3 + g];

    __shared__ __align__(16) float h_s[Hd];
    __shared__ float gh_s[G3];
    __shared__ float gx_s[G3];
    if (g < Hd) h_s[g] = 0.0f;
    float hreg = 0.0f;  // valid for g < Hd: this thread's h component

    const int t0 = (d == 0) ? 0 : (Lseq - 1);
    const int tstep = (d == 0) ? 1 : -1;

    float w0g = 0.0f, bi0 = 0.0f;
    const float* xs = nullptr;
    const float* gxp = nullptr;
    if (layer == 0) {
        w0g = w_ih0[d * G3 + g];
        bi0 = b_ih[d * G3 + g];
        xs = x + (size_t)b * Lseq + t0;
    } else {
        gxp = g_gx + (((size_t)d * Bsz + b) * Lseq + t0) * G3 + g;
    }
    float* outp = g_buf + (size_t)b * Lseq * IN2H + d * Hd + g;
    const long gstep = (long)tstep * G3;

    __syncthreads();

    // depth-4 prefetch ring
    float q[4];
#pragma unroll
    for (int j = 0; j < 4; j++)
        q[j] = (layer == 0) ? xs[(long)j * tstep] : gxp[(long)j * gstep];

#pragma unroll 1
    for (int s0 = 0; s0 < Lseq; s0 += 4) {
#pragma unroll
        for (int j = 0; j < 4; j++) {
            const int s = s0 + j;
            float raw = q[j];
            const int sp = s + 4;
            if (sp < Lseq)
                q[j] = (layer == 0) ? xs[(long)sp * tstep]
                                    : gxp[(long)sp * gstep];
            float gx_cur = (layer == 0) ? fmaf(raw, w0g, bi0) : raw;

            // gh[g] = bias + dot(w_hh[g], h) — 4 parallel f32x2 chains
            unsigned long long acc0 = 0ULL, acc1 = 0ULL, acc2 = 0ULL, acc3 = 0ULL;
            const ulonglong2* h4 = (const ulonglong2*)h_s;
#pragma unroll
            for (int i = 0; i < 8; i++) {
                ulonglong2 hv0 = h4[2 * i];
                ulonglong2 hv1 = h4[2 * i + 1];
                acc0 = fma2(w2[4 * i + 0], hv0.x, acc0);
                acc1 = fma2(w2[4 * i + 1], hv0.y, acc1);
                acc2 = fma2(w2[4 * i + 2], hv1.x, acc2);
                acc3 = fma2(w2[4 * i + 3], hv1.y, acc3);
            }
            float2 f0 = u2f2(acc0);
            float2 f1 = u2f2(acc1);
            float2 f2 = u2f2(acc2);
            float2 f3 = u2f2(acc3);
            float gh = ((f0.x + f0.y) + (f1.x + f1.y)) +
                       ((f2.x + f2.y) + (f3.x + f3.y)) + bias;

            gh_s[g] = gh;
            gx_s[g] = gx_cur;
            __syncthreads();

            if (g < Hd) {
                float r = sigm_fast(gx_s[g] + gh_s[g]);
                float z = sigm_fast(gx_s[Hd + g] + gh_s[Hd + g]);
                float n = tanh_fast(fmaf(r, gh_s[2 * Hd + g], gx_s[2 * Hd + g]));
                float hn = fmaf(z, hreg - n, n);  // (1-z)n + z*h
                hreg = hn;
                h_s[g] = hn;
                outp[(size_t)(t0 + s * tstep) * IN2H] = hn;
            }
            __syncthreads();
        }
    }
}

// ---------------- final FC on last timestep ----------------
__global__ void fc_kernel(const float* __restrict__ fc_w,
                          const float* __restrict__ fc_b,
                          float* __restrict__ out) {
    int b = blockIdx.x;
    int c = threadIdx.x;
    __shared__ float last[IN2H];
    if (threadIdx.x < IN2H)
        last[threadIdx.x] =
            g_buf[((size_t)b * Lseq + (Lseq - 1)) * IN2H + threadIdx.x];
    __syncthreads();
    if (c < NCLS) {
        float s = fc_b[c];
        const float* w = fc_w + (size_t)c * IN2H;
#pragma unroll 8
        for (int k = 0; k < IN2H; k++) s += last[k] * w[k];
        out[(size_t)b * NCLS + c] = s;
    }
}

extern "C" void kernel_launch(void* const* d_in, const int* in_sizes, int n_in,
                              void* d_out, int out_size) {
    const float* x     = (const float*)d_in[0];
    const float* w_ih0 = (const float*)d_in[1];
    const float* w_ih  = (const float*)d_in[2];
    const float* w_hh  = (const float*)d_in[3];
    const float* b_ih  = (const float*)d_in[4];
    const float* b_hh  = (const float*)d_in[5];
    const float* fc_w  = (const float*)d_in[6];
    const float* fc_b  = (const float*)d_in[7];
    float* out = (float*)d_out;

    // Layer 0: gx fused into the scan (input size 1)
    scan_kernel<<<dim3(Bsz, 2), 192>>>(w_hh, b_hh, x, w_ih0, b_ih, 0);
    // Layers 1..3: GEMM input projection, then scan
    for (int l = 1; l < 4; l++) {
        gx_gemm_kernel<<<dim3(BL / 64, 2), 256>>>(w_ih, b_ih, l);
        scan_kernel<<<dim3(Bsz, 2), 192>>>(w_hh, b_hh, x, w_ih0, b_ih, l);
    }
    fc_kernel<<<Bsz, 256>>>(fc_w, fc_b, out);
}

// round 4
// speedup vs baseline: 1.0071x; 1.0071x over previous
#include <cuda_runtime.h>

#define Bsz   128
#define Lseq  4096
#define Hd    64
#define G3    192
#define IN2H  128
#define NCLS  230
#define BL    (Bsz * Lseq)

// Scratch (allocation-free rule: __device__ globals)
__device__ float g_gx[(size_t)2 * BL * G3];    // [dir][b][t][192]  (~805 MB)
__device__ float g_buf[(size_t)BL * IN2H];     // [b][t][128]       (~268 MB)

// ---------------- packed f32x2 / fast-math helpers ----------------
__device__ __forceinline__ unsigned long long fma2(unsigned long long a,
                                                   unsigned long long b,
                                                   unsigned long long c) {
    unsigned long long d;
    asm("fma.rn.f32x2 %0, %1, %2, %3;" : "=l"(d) : "l"(a), "l"(b), "l"(c));
    return d;
}
__device__ __forceinline__ float2 u2f2(unsigned long long v) {
    float2 f;
    asm("mov.b64 {%0, %1}, %2;" : "=f"(f.x), "=f"(f.y) : "l"(v));
    return f;
}
__device__ __forceinline__ float tanh_fast(float x) {
    float y;
    asm("tanh.approx.f32 %0, %1;" : "=f"(y) : "f"(x));
    return y;
}
__device__ __forceinline__ float sigm_fast(float x) {
    // sigmoid(x) = 0.5*tanh(0.5x) + 0.5 — single MUFU.TANH
    return fmaf(0.5f, tanh_fast(0.5f * x), 0.5f);
}

// ---------------- gx GEMM for layers 1..3 ----------------
// gx[d][row][c] = sum_k inp[row][k] * w_ih[l-1][d][c][k] + b_ih[l][d][c]
// Tile: 64 rows x 192 cols, K=128 in 4 chunks of 32 (16 f32x2 pairs).
__global__ void __launch_bounds__(256, 1)
gx_gemm_kernel(const float* __restrict__ w_ih,
               const float* __restrict__ b_ih,
               int layer) {
    const int d = blockIdx.y;
    const size_t row0 = (size_t)blockIdx.x * 64;
    const int tid = threadIdx.x;
    const int tx = tid & 15;   // col group: cols tx + 16*j, j<12
    const int ty = tid >> 4;   // row group: rows ty + 16*i, i<4

    const unsigned long long* inp2 = (const unsigned long long*)g_buf;
    const unsigned long long* w2g =
        (const unsigned long long*)(w_ih + ((size_t)(layer - 1) * 2 + d) * G3 * IN2H);

    __shared__ unsigned long long a_s[16][65];   // [kpair][row]
    __shared__ unsigned long long b_s[16][193];  // [kpair][col]

    unsigned long long acc[4][12];
#pragma unroll
    for (int i = 0; i < 4; i++)
#pragma unroll
        for (int j = 0; j < 12; j++) acc[i][j] = 0ULL;

#pragma unroll 1
    for (int ch = 0; ch < 4; ch++) {
        const int kp2 = ch * 16;  // base k-pair index (ull units)
#pragma unroll
        for (int it = 0; it < 4; it++) {
            int lin = tid + it * 256;
            int r = lin >> 4;
            int c2 = lin & 15;
            a_s[c2][r] = inp2[(row0 + r) * 64 + kp2 + c2];
        }
#pragma unroll
        for (int it = 0; it < 12; it++) {
            int lin = tid + it * 256;
            int cc = lin >> 4;
            int c2 = lin & 15;
            b_s[c2][cc] = w2g[(size_t)cc * 64 + kp2 + c2];
        }
        __syncthreads();
#pragma unroll
        for (int kp = 0; kp < 16; kp++) {
            unsigned long long a2[4], b2[12];
#pragma unroll
            for (int i = 0; i < 4; i++) a2[i] = a_s[kp][ty + 16 * i];
#pragma unroll
            for (int j = 0; j < 12; j++) b2[j] = b_s[kp][tx + 16 * j];
#pragma unroll
            for (int i = 0; i < 4; i++)
#pragma unroll
                for (int j = 0; j < 12; j++)
                    acc[i][j] = fma2(a2[i], b2[j], acc[i][j]);
        }
        __syncthreads();
    }

    const float* bih = b_ih + ((size_t)layer * 2 + d) * G3;
#pragma unroll
    for (int i = 0; i < 4; i++) {
        size_t row = row0 + ty + 16 * i;
#pragma unroll
        for (int j = 0; j < 12; j++) {
            int c = tx + 16 * j;
            float2 f = u2f2(acc[i][j]);
            g_gx[((size_t)d * BL + row) * G3 + c] = f.x + f.y + bih[c];
        }
    }
}

// ---------------- sequential GRU scan ----------------
// grid (B, 2 dirs), 192 threads (one per gate output).
// layer 0: gx computed inline from x (input size 1). layers>=1: gx streamed
// from g_gx with a depth-4 register prefetch ring to hide DRAM latency.
__global__ void __launch_bounds__(192, 2)
scan_kernel(const float* __restrict__ w_hh,
            const float* __restrict__ b_hh,
            const float* __restrict__ x,
            const float* __restrict__ w_ih0,
            const float* __restrict__ b_ih,
            int layer) {
    const int b = blockIdx.x;
    const int d = blockIdx.y;
    const int g = threadIdx.x;

    // w_hh row for this gate output, packed as f32x2
    const float* W = w_hh + (((size_t)layer * 2 + d) * G3 + g) * Hd;
    unsigned long long w2[32];
#pragma unroll
    for (int i = 0; i < 32; i++) w2[i] = ((const unsigned long long*)W)[i];
    const float bias = b_hh[((size_t)layer * 2 + d) * G3 + g];

    __shared__ __align__(16) float h_s[Hd];
    __shared__ float gh_s[G3];
    __shared__ float gx_s[G3];
    if (g < Hd) h_s[g] = 0.0f;
    float hreg = 0.0f;  // valid for g < Hd: this thread's h component

    const int t0 = (d == 0) ? 0 : (Lseq - 1);
    const int tstep = (d == 0) ? 1 : -1;

    float w0g = 0.0f, bi0 = 0.0f;
    const float* xs = nullptr;
    const float* gxp = nullptr;
    if (layer == 0) {
        w0g = w_ih0[d * G3 + g];
        bi0 = b_ih[d * G3 + g];
        xs = x + (size_t)b * Lseq + t0;
    } else {
        gxp = g_gx + (((size_t)d * Bsz + b) * Lseq + t0) * G3 + g;
    }
    float* outp = g_buf + (size_t)b * Lseq * IN2H + d * Hd + g;
    const long gstep = (long)tstep * G3;

    __syncthreads();

    // depth-4 prefetch ring
    float q[4];
#pragma unroll
    for (int j = 0; j < 4; j++)
        q[j] = (layer == 0) ? xs[(long)j * tstep] : gxp[(long)j * gstep];

#pragma unroll 1
    for (int s0 = 0; s0 < Lseq; s0 += 4) {
#pragma unroll
        for (int j = 0; j < 4; j++) {
            const int s = s0 + j;
            float raw = q[j];
            const int sp = s + 4;
            if (sp < Lseq)
                q[j] = (layer == 0) ? xs[(long)sp * tstep]
                                    : gxp[(long)sp * gstep];
            float gx_cur = (layer == 0) ? fmaf(raw, w0g, bi0) : raw;

            // gh[g] = bias + dot(w_hh[g], h) — 4 parallel f32x2 chains
            unsigned long long acc0 = 0ULL, acc1 = 0ULL, acc2 = 0ULL, acc3 = 0ULL;
            const ulonglong2* h4 = (const ulonglong2*)h_s;
#pragma unroll
            for (int i = 0; i < 8; i++) {
                ulonglong2 hv0 = h4[2 * i];
                ulonglong2 hv1 = h4[2 * i + 1];
                acc0 = fma2(w2[4 * i + 0], hv0.x, acc0);
                acc1 = fma2(w2[4 * i + 1], hv0.y, acc1);
                acc2 = fma2(w2[4 * i + 2], hv1.x, acc2);
                acc3 = fma2(w2[4 * i + 3], hv1.y, acc3);
            }
            float2 f0 = u2f2(acc0);
            float2 f1 = u2f2(acc1);
            float2 f2 = u2f2(acc2);
            float2 f3 = u2f2(acc3);
            float gh = ((f0.x + f0.y) + (f1.x + f1.y)) +
                       ((f2.x + f2.y) + (f3.x + f3.y)) + bias;

            gh_s[g] = gh;
            gx_s[g] = gx_cur;
            __syncthreads();

            if (g < Hd) {
                float r = sigm_fast(gx_s[g] + gh_s[g]);
                float z = sigm_fast(gx_s[Hd + g] + gh_s[Hd + g]);
                float n = tanh_fast(fmaf(r, gh_s[2 * Hd + g], gx_s[2 * Hd + g]));
                float hn = fmaf(z, hreg - n, n);  // (1-z)n + z*h
                hreg = hn;
                h_s[g] = hn;
                outp[(size_t)(t0 + s * tstep) * IN2H] = hn;
            }
            __syncthreads();
        }
    }
}

// ---------------- final FC on last timestep ----------------
__global__ void fc_kernel(const float* __restrict__ fc_w,
                          const float* __restrict__ fc_b,
                          float* __restrict__ out) {
    int b = blockIdx.x;
    int c = threadIdx.x;
    __shared__ float last[IN2H];
    if (threadIdx.x < IN2H)
        last[threadIdx.x] =
            g_buf[((size_t)b * Lseq + (Lseq - 1)) * IN2H + threadIdx.x];
    __syncthreads();
    if (c < NCLS) {
        float s = fc_b[c];
        const float* w = fc_w + (size_t)c * IN2H;
#pragma unroll 8
        for (int k = 0; k < IN2H; k++) s += last[k] * w[k];
        out[(size_t)b * NCLS + c] = s;
    }
}

extern "C" void kernel_launch(void* const* d_in, const int* in_sizes, int n_in,
                              void* d_out, int out_size) {
    const float* x     = (const float*)d_in[0];
    const float* w_ih0 = (const float*)d_in[1];
    const float* w_ih  = (const float*)d_in[2];
    const float* w_hh  = (const float*)d_in[3];
    const float* b_ih  = (const float*)d_in[4];
    const float* b_hh  = (const float*)d_in[5];
    const float* fc_w  = (const float*)d_in[6];
    const float* fc_b  = (const float*)d_in[7];
    float* out = (float*)d_out;

    // Layer 0: gx fused into the scan (input size 1)
    scan_kernel<<<dim3(Bsz, 2), 192>>>(w_hh, b_hh, x, w_ih0, b_ih, 0);
    // Layers 1..3: GEMM input projection, then scan
    for (int l = 1; l < 4; l++) {
        gx_gemm_kernel<<<dim3(BL / 64, 2), 256>>>(w_ih, b_ih, l);
        scan_kernel<<<dim3(Bsz, 2), 192>>>(w_hh, b_hh, x, w_ih0, b_ih, l);
    }
    fc_kernel<<<Bsz, 256>>>(fc_w, fc_b, out);
}

// round 5
// speedup vs baseline: 1.0077x; 1.0006x over previous
#include <cuda_runtime.h>

#define Bsz   128
#define Lseq  4096
#define Hd    64
#define G3    192
#define IN2H  128
#define NCLS  230
#define BL    (Bsz * Lseq)

// Scratch (allocation-free rule: __device__ globals)
__device__ float g_gx[(size_t)2 * BL * G3];    // [dir][b][t][192]  (~805 MB)
__device__ float g_buf[(size_t)BL * IN2H];     // [b][t][128]       (~268 MB)

// ---------------- packed f32x2 / fast-math helpers ----------------
__device__ __forceinline__ unsigned long long fma2(unsigned long long a,
                                                   unsigned long long b,
                                                   unsigned long long c) {
    unsigned long long d;
    asm("fma.rn.f32x2 %0, %1, %2, %3;" : "=l"(d) : "l"(a), "l"(b), "l"(c));
    return d;
}
__device__ __forceinline__ float2 u2f2(unsigned long long v) {
    float2 f;
    asm("mov.b64 {%0, %1}, %2;" : "=f"(f.x), "=f"(f.y) : "l"(v));
    return f;
}
__device__ __forceinline__ float tanh_fast(float x) {
    float y;
    asm("tanh.approx.f32 %0, %1;" : "=f"(y) : "f"(x));
    return y;
}
__device__ __forceinline__ float sigm_fast(float x) {
    // sigmoid(x) = 0.5*tanh(0.5x) + 0.5 — single MUFU.TANH
    return fmaf(0.5f, tanh_fast(0.5f * x), 0.5f);
}

// ---------------- gx GEMM for layers 1..3 ----------------
// gx[d][row][c] = sum_k inp[row][k] * w_ih[l-1][d][c][k] + b_ih[l][d][c]
// Tile: 64 rows x 192 cols, K=128 in 4 chunks of 32 (16 f32x2 pairs).
__global__ void __launch_bounds__(256, 1)
gx_gemm_kernel(const float* __restrict__ w_ih,
               const float* __restrict__ b_ih,
               int layer) {
    const int d = blockIdx.y;
    const size_t row0 = (size_t)blockIdx.x * 64;
    const int tid = threadIdx.x;
    const int tx = tid & 15;   // col group: cols tx + 16*j, j<12
    const int ty = tid >> 4;   // row group: rows ty + 16*i, i<4

    const unsigned long long* inp2 = (const unsigned long long*)g_buf;
    const unsigned long long* w2g =
        (const unsigned long long*)(w_ih + ((size_t)(layer - 1) * 2 + d) * G3 * IN2H);

    __shared__ unsigned long long a_s[16][65];   // [kpair][row]
    __shared__ unsigned long long b_s[16][193];  // [kpair][col]

    unsigned long long acc[4][12];
#pragma unroll
    for (int i = 0; i < 4; i++)
#pragma unroll
        for (int j = 0; j < 12; j++) acc[i][j] = 0ULL;

#pragma unroll 1
    for (int ch = 0; ch < 4; ch++) {
        const int kp2 = ch * 16;  // base k-pair index (ull units)
#pragma unroll
        for (int it = 0; it < 4; it++) {
            int lin = tid + it * 256;
            int r = lin >> 4;
            int c2 = lin & 15;
            a_s[c2][r] = inp2[(row0 + r) * 64 + kp2 + c2];
        }
#pragma unroll
        for (int it = 0; it < 12; it++) {
            int lin = tid + it * 256;
            int cc = lin >> 4;
            int c2 = lin & 15;
            b_s[c2][cc] = w2g[(size_t)cc * 64 + kp2 + c2];
        }
        __syncthreads();
#pragma unroll
        for (int kp = 0; kp < 16; kp++) {
            unsigned long long a2[4], b2[12];
#pragma unroll
            for (int i = 0; i < 4; i++) a2[i] = a_s[kp][ty + 16 * i];
#pragma unroll
            for (int j = 0; j < 12; j++) b2[j] = b_s[kp][tx + 16 * j];
#pragma unroll
            for (int i = 0; i < 4; i++)
#pragma unroll
                for (int j = 0; j < 12; j++)
                    acc[i][j] = fma2(a2[i], b2[j], acc[i][j]);
        }
        __syncthreads();
    }

    const float* bih = b_ih + ((size_t)layer * 2 + d) * G3;
#pragma unroll
    for (int i = 0; i < 4; i++) {
        size_t row = row0 + ty + 16 * i;
#pragma unroll
        for (int j = 0; j < 12; j++) {
            int c = tx + 16 * j;
            float2 f = u2f2(acc[i][j]);
            g_gx[((size_t)d * BL + row) * G3 + c] = f.x + f.y + bih[c];
        }
    }
}

// ---------------- sequential GRU scan ----------------
// grid (B, 2 dirs), 192 threads (one per gate output).
// layer 0: gx computed inline from x (input size 1). layers>=1: gx streamed
// from g_gx with a depth-4 register prefetch ring to hide DRAM latency.
__global__ void __launch_bounds__(192, 2)
scan_kernel(const float* __restrict__ w_hh,
            const float* __restrict__ b_hh,
            const float* __restrict__ x,
            const float* __restrict__ w_ih0,
            const float* __restrict__ b_ih,
            int layer) {
    const int b = blockIdx.x;
    const int d = blockIdx.y;
    const int g = threadIdx.x;

    // w_hh row for this gate output, packed as f32x2
    const float* W = w_hh + (((size_t)layer * 2 + d) * G3 + g) * Hd;
    unsigned long long w2[32];
#pragma unroll
    for (int i = 0; i < 32; i++) w2[i] = ((const unsigned long long*)W)[i];
    const float bias = b_hh[((size_t)layer * 2 + d) * G3 + g];

    __shared__ __align__(16) float h_s[Hd];
    __shared__ float gh_s[G3];
    __shared__ float gx_s[G3];
    if (g < Hd) h_s[g] = 0.0f;
    float hreg = 0.0f;  // valid for g < Hd: this thread's h component

    const int t0 = (d == 0) ? 0 : (Lseq - 1);
    const int tstep = (d == 0) ? 1 : -1;

    float w0g = 0.0f, bi0 = 0.0f;
    const float* xs = nullptr;
    const float* gxp = nullptr;
    if (layer == 0) {
        w0g = w_ih0[d * G3 + g];
        bi0 = b_ih[d * G3 + g];
        xs = x + (size_t)b * Lseq + t0;
    } else {
        gxp = g_gx + (((size_t)d * Bsz + b) * Lseq + t0) * G3 + g;
    }
    float* outp = g_buf + (size_t)b * Lseq * IN2H + d * Hd + g;
    const long gstep = (long)tstep * G3;

    __syncthreads();

    // depth-4 prefetch ring
    float q[4];
#pragma unroll
    for (int j = 0; j < 4; j++)
        q[j] = (layer == 0) ? xs[(long)j * tstep] : gxp[(long)j * gstep];

#pragma unroll 1
    for (int s0 = 0; s0 < Lseq; s0 += 4) {
#pragma unroll
        for (int j = 0; j < 4; j++) {
            const int s = s0 + j;
            float raw = q[j];
            const int sp = s + 4;
            if (sp < Lseq)
                q[j] = (layer == 0) ? xs[(long)sp * tstep]
                                    : gxp[(long)sp * gstep];
            float gx_cur = (layer == 0) ? fmaf(raw, w0g, bi0) : raw;

            // gh[g] = bias + dot(w_hh[g], h) — 4 parallel f32x2 chains
            unsigned long long acc0 = 0ULL, acc1 = 0ULL, acc2 = 0ULL, acc3 = 0ULL;
            const ulonglong2* h4 = (const ulonglong2*)h_s;
#pragma unroll
            for (int i = 0; i < 8; i++) {
                ulonglong2 hv0 = h4[2 * i];
                ulonglong2 hv1 = h4[2 * i + 1];
                acc0 = fma2(w2[4 * i + 0], hv0.x, acc0);
                acc1 = fma2(w2[4 * i + 1], hv0.y, acc1);
                acc2 = fma2(w2[4 * i + 2], hv1.x, acc2);
                acc3 = fma2(w2[4 * i + 3], hv1.y, acc3);
            }
            float2 f0 = u2f2(acc0);
            float2 f1 = u2f2(acc1);
            float2 f2 = u2f2(acc2);
            float2 f3 = u2f2(acc3);
            float gh = ((f0.x + f0.y) + (f1.x + f1.y)) +
                       ((f2.x + f2.y) + (f3.x + f3.y)) + bias;

            gh_s[g] = gh;
            gx_s[g] = gx_cur;
            __syncthreads();

            if (g < Hd) {
                float r = sigm_fast(gx_s[g] + gh_s[g]);
                float z = sigm_fast(gx_s[Hd + g] + gh_s[Hd + g]);
                float n = tanh_fast(fmaf(r, gh_s[2 * Hd + g], gx_s[2 * Hd + g]));
                float hn = fmaf(z, hreg - n, n);  // (1-z)n + z*h
                hreg = hn;
                h_s[g] = hn;
                outp[(size_t)(t0 + s * tstep) * IN2H] = hn;
            }
            __syncthreads();
        }
    }
}

// ---------------- final FC on last timestep ----------------
__global__ void fc_kernel(const float* __restrict__ fc_w,
                          const float* __restrict__ fc_b,
                          float* __restrict__ out) {
    int b = blockIdx.x;
    int c = threadIdx.x;
    __shared__ float last[IN2H];
    if (threadIdx.x < IN2H)
        last[threadIdx.x] =
            g_buf[((size_t)b * Lseq + (Lseq - 1)) * IN2H + threadIdx.x];
    __syncthreads();
    if (c < NCLS) {
        float s = fc_b[c];
        const float* w = fc_w + (size_t)c * IN2H;
#pragma unroll 8
        for (int k = 0; k < IN2H; k++) s += last[k] * w[k];
        out[(size_t)b * NCLS + c] = s;
    }
}

extern "C" void kernel_launch(void* const* d_in, const int* in_sizes, int n_in,
                              void* d_out, int out_size) {
    const float* x     = (const float*)d_in[0];
    const float* w_ih0 = (const float*)d_in[1];
    const float* w_ih  = (const float*)d_in[2];
    const float* w_hh  = (const float*)d_in[3];
    const float* b_ih  = (const float*)d_in[4];
    const float* b_hh  = (const float*)d_in[5];
    const float* fc_w  = (const float*)d_in[6];
    const float* fc_b  = (const float*)d_in[7];
    float* out = (float*)d_out;

    // Layer 0: gx fused into the scan (input size 1)
    scan_kernel<<<dim3(Bsz, 2), 192>>>(w_hh, b_hh, x, w_ih0, b_ih, 0);
    // Layers 1..3: GEMM input projection, then scan
    for (int l = 1; l < 4; l++) {
        gx_gemm_kernel<<<dim3(BL / 64, 2), 256>>>(w_ih, b_ih, l);
        scan_kernel<<<dim3(Bsz, 2), 192>>>(w_hh, b_hh, x, w_ih0, b_ih, l);
    }
    fc_kernel<<<Bsz, 256>>>(fc_w, fc_b, out);
}